// round 1
// baseline (speedup 1.0000x reference)
#include <cuda_runtime.h>
#include <cstdint>

// ---------------------------------------------------------------------------
// RNN-T joint network:
//   XT = x@W_tr + b_tr            [1600, 256]
//   YP = y@W_pr + b_pr            [400, 256]
//   Z  = tf32(tanh(XT[bt] + YP[b,u]))   [160000, 256]
//   out= Z @ W_cls + b_cls        [160000, 1024]
// ---------------------------------------------------------------------------

#define B_  4
#define T_  400
#define U_  100
#define DTR 768
#define DPR 640
#define DJ  256
#define V_  1024
#define M_TOTAL (B_ * T_ * U_)   // 160000

// scratch (alloc-free rule: __device__ globals)
__device__ float g_XT[(size_t)B_ * T_ * DJ];      // 1600*256
__device__ float g_YP[(size_t)B_ * U_ * DJ];      // 400*256
__device__ float g_Z[(size_t)M_TOTAL * DJ];       // 160000*256 = 164 MB

__device__ __forceinline__ float to_tf32(float f) {
    uint32_t u;
    asm("cvt.rna.tf32.f32 %0, %1;" : "=r"(u) : "f"(f));
    return __uint_as_float(u);
}

__device__ __forceinline__ void mma_tf32(float* c, const uint32_t* a, const uint32_t* b) {
    asm volatile(
        "mma.sync.aligned.m16n8k8.row.col.f32.tf32.tf32.f32 "
        "{%0,%1,%2,%3}, {%4,%5,%6,%7}, {%8,%9}, {%0,%1,%2,%3};\n"
        : "+f"(c[0]), "+f"(c[1]), "+f"(c[2]), "+f"(c[3])
        : "r"(a[0]), "r"(a[1]), "r"(a[2]), "r"(a[3]), "r"(b[0]), "r"(b[1]));
}

// ---------------------------------------------------------------------------
// Stage 1: small fp32 GEMM with bias, C[M,256] = A[M,K] @ W[K,256] + bias
// tile 64x64x16, 256 threads, 4x4 micro-tile. K must be divisible by 16.
// ---------------------------------------------------------------------------
__global__ __launch_bounds__(256)
void gemm_bias_f32(const float* __restrict__ A, const float* __restrict__ W,
                   const float* __restrict__ bias, float* __restrict__ C,
                   int M, int K) {
    const int N = DJ;  // 256
    __shared__ float As[16][68];
    __shared__ float Ws[16][68];

    int m0 = blockIdx.x * 64, n0 = blockIdx.y * 64;
    int tid = threadIdx.x;
    int ty = tid >> 4, tx = tid & 15;

    float acc[4][4];
#pragma unroll
    for (int i = 0; i < 4; i++)
#pragma unroll
        for (int j = 0; j < 4; j++) acc[i][j] = 0.f;

    for (int k0 = 0; k0 < K; k0 += 16) {
        // A tile: 64 rows x 16 k, one float4 per thread
        {
            int row = tid >> 2, kc = (tid & 3) << 2;
            float4 v = make_float4(0.f, 0.f, 0.f, 0.f);
            int m = m0 + row;
            if (m < M) v = *(const float4*)(A + (size_t)m * K + k0 + kc);
            As[kc + 0][row] = v.x;
            As[kc + 1][row] = v.y;
            As[kc + 2][row] = v.z;
            As[kc + 3][row] = v.w;
        }
        // W tile: 16 rows x 64 n
        {
            int kr = tid >> 4, nc = (tid & 15) << 2;
            float4 w = *(const float4*)(W + (size_t)(k0 + kr) * N + n0 + nc);
            *(float4*)&Ws[kr][nc] = w;
        }
        __syncthreads();
#pragma unroll
        for (int kk = 0; kk < 16; kk++) {
            float a[4], b[4];
#pragma unroll
            for (int i = 0; i < 4; i++) a[i] = As[kk][ty * 4 + i];
#pragma unroll
            for (int j = 0; j < 4; j++) b[j] = Ws[kk][tx * 4 + j];
#pragma unroll
            for (int i = 0; i < 4; i++)
#pragma unroll
                for (int j = 0; j < 4; j++) acc[i][j] = fmaf(a[i], b[j], acc[i][j]);
        }
        __syncthreads();
    }

#pragma unroll
    for (int i = 0; i < 4; i++) {
        int m = m0 + ty * 4 + i;
        if (m >= M) continue;
#pragma unroll
        for (int j = 0; j < 4; j++) {
            int n = n0 + tx * 4 + j;
            C[(size_t)m * N + n] = acc[i][j] + bias[n];
        }
    }
}

// ---------------------------------------------------------------------------
// Stage 2: Z = tf32_round(tanh(XT[bt,:] + YP[b*U+u,:]))
// ---------------------------------------------------------------------------
__global__ __launch_bounds__(256)
void z_tanh_kernel(const float* __restrict__ XT, const float* __restrict__ YP,
                   float* __restrict__ Z) {
    int i = blockIdx.x * blockDim.x + threadIdx.x;      // float4 index
    const int total4 = M_TOTAL * (DJ / 4);              // 10,240,000
    if (i >= total4) return;
    int m = i >> 6;            // row in [0, 160000)
    int q = i & 63;            // float4 within row
    int bt = m / U_;           // b*T + t
    int u = m - bt * U_;
    int b = bt / T_;

    float4 xv = *(const float4*)(XT + (size_t)bt * DJ + q * 4);
    float4 yv = *(const float4*)(YP + (size_t)(b * U_ + u) * DJ + q * 4);
    float4 z;
    z.x = to_tf32(tanhf(xv.x + yv.x));
    z.y = to_tf32(tanhf(xv.y + yv.y));
    z.z = to_tf32(tanhf(xv.z + yv.z));
    z.w = to_tf32(tanhf(xv.w + yv.w));
    *(float4*)(Z + (size_t)m * DJ + q * 4) = z;
}

// ---------------------------------------------------------------------------
// Stage 3: out[160000,1024] = Z[160000,256] @ W_cls[256,1024] + b_cls
// tf32 mma.sync.m16n8k8. Block tile 128x128x32, 8 warps (2 M x 4 N),
// warp tile 64x32 => 4x4 fragment grid, 16 mma per k-step.
// gridDim = (8 N-tiles fastest, 1250 M-tiles) so 8 concurrent blocks share
// each Z tile via L2 (Z DRAM traffic ~1x instead of 8x).
// ---------------------------------------------------------------------------
#define BM 128
#define BN 128
#define BK 32

__global__ __launch_bounds__(256)
void joint_gemm_tf32(const float* __restrict__ Z, const float* __restrict__ W,
                     const float* __restrict__ bias, float* __restrict__ out) {
    __shared__ float As[BK][BM + 2];   // stride 130 (2-way max conflicts)
    __shared__ float Bs[BK][BN + 4];   // stride 132, float4-store aligned

    const int K = DJ;     // 256
    const int N = V_;     // 1024

    int n0 = blockIdx.x * BN;
    int m0 = blockIdx.y * BM;
    int tid = threadIdx.x;
    int lane = tid & 31, w = tid >> 5;
    int warpM = w & 1, warpN = w >> 1;          // 2 x 4 warp grid
    int wm0 = warpM * 64, wn0 = warpN * 32;
    int gid = lane >> 2, tig = lane & 3;

    float acc[4][4][4];
#pragma unroll
    for (int fm = 0; fm < 4; fm++)
#pragma unroll
        for (int fn = 0; fn < 4; fn++)
#pragma unroll
            for (int r = 0; r < 4; r++) acc[fm][fn][r] = 0.f;

    for (int k0 = 0; k0 < K; k0 += BK) {
        // A tile: 128 rows x 32 k. 8 threads/row, 4 passes of 32 rows.
        {
            int r = tid >> 3, c4 = (tid & 7) << 2;
#pragma unroll
            for (int p = 0; p < 4; p++) {
                int row = r + p * 32;
                float4 v = *(const float4*)(Z + (size_t)(m0 + row) * K + k0 + c4);
                As[c4 + 0][row] = v.x;
                As[c4 + 1][row] = v.y;
                As[c4 + 2][row] = v.z;
                As[c4 + 3][row] = v.w;
            }
        }
        // B tile: 32 rows x 128 n. One warp per row, 4 passes of 8 rows.
        {
            int br = tid >> 5, bc4 = (tid & 31) << 2;
#pragma unroll
            for (int p = 0; p < 4; p++) {
                int row = br + p * 8;
                float4 v = *(const float4*)(W + (size_t)(k0 + row) * N + n0 + bc4);
                v.x = to_tf32(v.x);
                v.y = to_tf32(v.y);
                v.z = to_tf32(v.z);
                v.w = to_tf32(v.w);
                *(float4*)&Bs[row][bc4] = v;
            }
        }
        __syncthreads();

#pragma unroll
        for (int kk = 0; kk < BK; kk += 8) {
            uint32_t a[4][4], b[4][2];
#pragma unroll
            for (int fm = 0; fm < 4; fm++) {
                int mr = wm0 + fm * 16 + gid;
                a[fm][0] = __float_as_uint(As[kk + tig][mr]);
                a[fm][1] = __float_as_uint(As[kk + tig][mr + 8]);
                a[fm][2] = __float_as_uint(As[kk + tig + 4][mr]);
                a[fm][3] = __float_as_uint(As[kk + tig + 4][mr + 8]);
            }
#pragma unroll
            for (int fn = 0; fn < 4; fn++) {
                int nc = wn0 + fn * 8 + gid;
                b[fn][0] = __float_as_uint(Bs[kk + tig][nc]);
                b[fn][1] = __float_as_uint(Bs[kk + tig + 4][nc]);
            }
#pragma unroll
            for (int fm = 0; fm < 4; fm++)
#pragma unroll
                for (int fn = 0; fn < 4; fn++) mma_tf32(acc[fm][fn], a[fm], b[fn]);
        }
        __syncthreads();
    }

    // epilogue: bias + store (float2 per fragment half)
#pragma unroll
    for (int fm = 0; fm < 4; fm++) {
        int r0 = m0 + wm0 + fm * 16 + gid;
#pragma unroll
        for (int fn = 0; fn < 4; fn++) {
            int c = n0 + wn0 + fn * 8 + 2 * tig;
            float bv0 = __ldg(bias + c);
            float bv1 = __ldg(bias + c + 1);
            float2 v0 = make_float2(acc[fm][fn][0] + bv0, acc[fm][fn][1] + bv1);
            float2 v1 = make_float2(acc[fm][fn][2] + bv0, acc[fm][fn][3] + bv1);
            *(float2*)(out + (size_t)r0 * N + c) = v0;
            *(float2*)(out + (size_t)(r0 + 8) * N + c) = v1;
        }
    }
}

// ---------------------------------------------------------------------------
extern "C" void kernel_launch(void* const* d_in, const int* in_sizes, int n_in,
                              void* d_out, int out_size) {
    const float* x     = (const float*)d_in[0];
    const float* y     = (const float*)d_in[1];
    const float* W_tr  = (const float*)d_in[2];
    const float* b_tr  = (const float*)d_in[3];
    const float* W_pr  = (const float*)d_in[4];
    const float* b_pr  = (const float*)d_in[5];
    const float* W_cls = (const float*)d_in[6];
    const float* b_cls = (const float*)d_in[7];
    float* out = (float*)d_out;

    void *pXT, *pYP, *pZ;
    cudaGetSymbolAddress(&pXT, g_XT);
    cudaGetSymbolAddress(&pYP, g_YP);
    cudaGetSymbolAddress(&pZ, g_Z);

    // XT = x @ W_tr + b_tr   (M=1600, K=768)
    {
        dim3 grid((B_ * T_ + 63) / 64, DJ / 64);
        gemm_bias_f32<<<grid, 256>>>(x, W_tr, b_tr, (float*)pXT, B_ * T_, DTR);
    }
    // YP = y @ W_pr + b_pr   (M=400, K=640)
    {
        dim3 grid((B_ * U_ + 63) / 64, DJ / 64);
        gemm_bias_f32<<<grid, 256>>>(y, W_pr, b_pr, (float*)pYP, B_ * U_, DPR);
    }
    // Z = tf32(tanh(XT + YP))
    {
        int total4 = M_TOTAL * (DJ / 4);
        z_tanh_kernel<<<(total4 + 255) / 256, 256>>>((const float*)pXT,
                                                     (const float*)pYP, (float*)pZ);
    }
    // out = Z @ W_cls + b_cls   (N-tiles fastest for Z L2 reuse)
    {
        dim3 grid(V_ / BN, M_TOTAL / BM);   // (8, 1250)
        joint_gemm_tf32<<<grid, 256>>>((const float*)pZ, W_cls, b_cls, out);
    }
}

// round 3
// speedup vs baseline: 1.3201x; 1.3201x over previous
#include <cuda_runtime.h>
#include <cstdint>

// ---------------------------------------------------------------------------
// RNN-T joint network (sm_103 plain: legacy tensor path, no tcgen05):
//   XT = x@W_tr + b_tr            [1600, 256]
//   YP = y@W_pr + b_pr            [400, 256]
//   Z  = tf32(tanh(XT[bt] + YP[b,u]))   [160000, 256]
//   out= Z @ W_cls + b_cls        [160000, 1024]   <- mma.sync tf32, conflict-free
// ---------------------------------------------------------------------------

#define B_  4
#define T_  400
#define U_  100
#define DTR 768
#define DPR 640
#define DJ  256
#define V_  1024
#define M_TOTAL (B_ * T_ * U_)   // 160000

__device__ float g_XT[(size_t)B_ * T_ * DJ];
__device__ float g_YP[(size_t)B_ * U_ * DJ];
__device__ float g_Z[(size_t)M_TOTAL * DJ];   // 164 MB, tf32-rounded
__device__ float g_Wr[(size_t)DJ * V_];       // tf32-rounded W_cls (same layout)

__device__ __forceinline__ float to_tf32(float f) {
    uint32_t u;
    asm("cvt.rna.tf32.f32 %0, %1;" : "=r"(u) : "f"(f));
    return __uint_as_float(u);
}

__device__ __forceinline__ void mma_tf32(float* c, const uint32_t* a, const uint32_t* b) {
    asm volatile(
        "mma.sync.aligned.m16n8k8.row.col.f32.tf32.tf32.f32 "
        "{%0,%1,%2,%3}, {%4,%5,%6,%7}, {%8,%9}, {%0,%1,%2,%3};\n"
        : "+f"(c[0]), "+f"(c[1]), "+f"(c[2]), "+f"(c[3])
        : "r"(a[0]), "r"(a[1]), "r"(a[2]), "r"(a[3]), "r"(b[0]), "r"(b[1]));
}

__device__ __forceinline__ uint32_t smem_u32(const void* p) {
    uint32_t a;
    asm("{ .reg .u64 t; cvta.to.shared.u64 t, %1; cvt.u32.u64 %0, t; }" : "=r"(a) : "l"(p));
    return a;
}

// ---------------------------------------------------------------------------
// Stage 0: g_Wr = tf32(W_cls)   (1 MB, trivial)
// ---------------------------------------------------------------------------
__global__ __launch_bounds__(256)
void round_w(const float* __restrict__ W, float* __restrict__ Wr) {
    int i = blockIdx.x * 256 + threadIdx.x;   // float4 index
    float4 v = *(const float4*)(W + (size_t)i * 4);
    v.x = to_tf32(v.x);
    v.y = to_tf32(v.y);
    v.z = to_tf32(v.z);
    v.w = to_tf32(v.w);
    *(float4*)(Wr + (size_t)i * 4) = v;
}

// ---------------------------------------------------------------------------
// Stage 1: small fp32 GEMM with bias, C[M,256] = A[M,K] @ W[K,256] + bias
// ---------------------------------------------------------------------------
__global__ __launch_bounds__(256)
void gemm_bias_f32(const float* __restrict__ A, const float* __restrict__ W,
                   const float* __restrict__ bias, float* __restrict__ C,
                   int M, int K) {
    const int N = DJ;
    __shared__ float As[16][68];
    __shared__ float Ws[16][68];

    int m0 = blockIdx.x * 64, n0 = blockIdx.y * 64;
    int tid = threadIdx.x;
    int ty = tid >> 4, tx = tid & 15;

    float acc[4][4];
#pragma unroll
    for (int i = 0; i < 4; i++)
#pragma unroll
        for (int j = 0; j < 4; j++) acc[i][j] = 0.f;

    for (int k0 = 0; k0 < K; k0 += 16) {
        {
            int row = tid >> 2, kc = (tid & 3) << 2;
            float4 v = make_float4(0.f, 0.f, 0.f, 0.f);
            int m = m0 + row;
            if (m < M) v = *(const float4*)(A + (size_t)m * K + k0 + kc);
            As[kc + 0][row] = v.x;
            As[kc + 1][row] = v.y;
            As[kc + 2][row] = v.z;
            As[kc + 3][row] = v.w;
        }
        {
            int kr = tid >> 4, nc = (tid & 15) << 2;
            float4 w = *(const float4*)(W + (size_t)(k0 + kr) * N + n0 + nc);
            *(float4*)&Ws[kr][nc] = w;
        }
        __syncthreads();
#pragma unroll
        for (int kk = 0; kk < 16; kk++) {
            float a[4], b[4];
#pragma unroll
            for (int i = 0; i < 4; i++) a[i] = As[kk][ty * 4 + i];
#pragma unroll
            for (int j = 0; j < 4; j++) b[j] = Ws[kk][tx * 4 + j];
#pragma unroll
            for (int i = 0; i < 4; i++)
#pragma unroll
                for (int j = 0; j < 4; j++) acc[i][j] = fmaf(a[i], b[j], acc[i][j]);
        }
        __syncthreads();
    }
#pragma unroll
    for (int i = 0; i < 4; i++) {
        int m = m0 + ty * 4 + i;
        if (m >= M) continue;
#pragma unroll
        for (int j = 0; j < 4; j++) {
            int n = n0 + tx * 4 + j;
            C[(size_t)m * N + n] = acc[i][j] + bias[n];
        }
    }
}

// ---------------------------------------------------------------------------
// Stage 2: Z = tf32_round(tanh(XT[bt,:] + YP[b*U+u,:]))
// ---------------------------------------------------------------------------
__global__ __launch_bounds__(256)
void z_tanh_kernel(const float* __restrict__ XT, const float* __restrict__ YP,
                   float* __restrict__ Z) {
    int i = blockIdx.x * blockDim.x + threadIdx.x;
    const int total4 = M_TOTAL * (DJ / 4);
    if (i >= total4) return;
    int m = i >> 6;
    int q = i & 63;
    int bt = m / U_;
    int u = m - bt * U_;
    int b = bt / T_;

    float4 xv = *(const float4*)(XT + (size_t)bt * DJ + q * 4);
    float4 yv = *(const float4*)(YP + (size_t)(b * U_ + u) * DJ + q * 4);
    float4 z;
    z.x = to_tf32(tanhf(xv.x + yv.x));
    z.y = to_tf32(tanhf(xv.y + yv.y));
    z.z = to_tf32(tanhf(xv.z + yv.z));
    z.w = to_tf32(tanhf(xv.w + yv.w));
    *(float4*)(Z + (size_t)m * DJ + q * 4) = z;
}

// ---------------------------------------------------------------------------
// Stage 3: out[160000,1024] = Z @ W_cls + b_cls  via mma.sync tf32.
// Block 128x128x32, 256 threads, warp tile 64x32 (2x4 warp grid).
// SMEM layouts chosen for conflict-free fragment feeds:
//   A row-major [128][36]  (stride 36 % 32 == 4  -> bank = 4*gid + tig, 0-conflict)
//   B k-major  [32][136]   (stride 136 % 32 == 8 -> bank = gid + 8*tig, 0-conflict)
// Double-buffered cp.async.cg loads. N-tiles fastest in grid for Z L2 reuse.
// ---------------------------------------------------------------------------
#define BM 128
#define BN 128
#define BK 32
#define A_STRIDE 36
#define B_STRIDE 136
#define A_BYTES (BM * A_STRIDE * 4)   // 18432
#define B_BYTES (BK * B_STRIDE * 4)   // 17408
#define SMEM_TOTAL_BYTES (2 * (A_BYTES + B_BYTES))  // 71680

__global__ __launch_bounds__(256)
void joint_gemm_tf32(const float* __restrict__ Z, const float* __restrict__ W,
                     const float* __restrict__ bias, float* __restrict__ out) {
    extern __shared__ char sm[];
    float* const Abuf[2] = { (float*)sm, (float*)(sm + A_BYTES) };
    float* const Bbuf[2] = { (float*)(sm + 2 * A_BYTES),
                             (float*)(sm + 2 * A_BYTES + B_BYTES) };

    const int K = DJ;     // 256
    const int N = V_;     // 1024

    const int n0 = blockIdx.x * BN;
    const int m0 = blockIdx.y * BM;
    const int tid = threadIdx.x;
    const int lane = tid & 31, w = tid >> 5;
    const int warpM = w & 1, warpN = w >> 1;    // 2 x 4 warp grid
    const int wm0 = warpM * 64, wn0 = warpN * 32;
    const int gid = lane >> 2, tig = lane & 3;

    // cp.async source/dest precompute
    // A: thread t covers row = t>>1 (128 rows), 4 float4 at col4 = (t&1)*4 + i
    const int a_row = tid >> 1;
    const int a_c4 = (tid & 1) * 4;
    const float* a_src = Z + (size_t)(m0 + a_row) * K + a_c4 * 4;
    const uint32_t a_dst = smem_u32(sm) + (uint32_t)(a_row * A_STRIDE + a_c4 * 4) * 4;
    // B: thread t covers row = t>>3 (32 rows), 4 float4 at col4 = (t&7) + 8*i
    const int b_row = tid >> 3;
    const int b_c4 = tid & 7;
    const float* b_src = W + (size_t)b_row * N + n0 + b_c4 * 4;
    const uint32_t b_dst = smem_u32(sm) + 2 * A_BYTES +
                           (uint32_t)(b_row * B_STRIDE + b_c4 * 4) * 4;

#define LOAD_TILE(c, buf) do { \
    const float* _as = a_src + (c) * BK; \
    uint32_t _ad = a_dst + (buf) * A_BYTES; \
    _Pragma("unroll") \
    for (int i = 0; i < 4; i++) \
        asm volatile("cp.async.cg.shared.global [%0], [%1], 16;" \
                     :: "r"(_ad + i * 16), "l"(_as + i * 4)); \
    const float* _bs = b_src + (size_t)(c) * BK * N; \
    uint32_t _bd = b_dst + (buf) * B_BYTES; \
    _Pragma("unroll") \
    for (int i = 0; i < 4; i++) \
        asm volatile("cp.async.cg.shared.global [%0], [%1], 16;" \
                     :: "r"(_bd + i * 8 * 16), "l"(_bs + i * 8 * 4)); \
    asm volatile("cp.async.commit_group;" ::: "memory"); \
} while (0)

    float acc[4][4][4];
#pragma unroll
    for (int fm = 0; fm < 4; fm++)
#pragma unroll
        for (int fn = 0; fn < 4; fn++)
#pragma unroll
            for (int r = 0; r < 4; r++) acc[fm][fn][r] = 0.f;

    LOAD_TILE(0, 0);
    LOAD_TILE(1, 1);

#pragma unroll 1
    for (int c = 0; c < 8; c++) {
        const int buf = c & 1;
        if (c < 7) asm volatile("cp.async.wait_group 1;" ::: "memory");
        else       asm volatile("cp.async.wait_group 0;" ::: "memory");
        __syncthreads();

        const float* As = Abuf[buf];
        const float* Bs = Bbuf[buf];
#pragma unroll
        for (int kk = 0; kk < BK; kk += 8) {
            uint32_t a[4][4], b[4][2];
#pragma unroll
            for (int fm = 0; fm < 4; fm++) {
                int mr = wm0 + fm * 16 + gid;
                a[fm][0] = __float_as_uint(As[mr * A_STRIDE + kk + tig]);
                a[fm][1] = __float_as_uint(As[(mr + 8) * A_STRIDE + kk + tig]);
                a[fm][2] = __float_as_uint(As[mr * A_STRIDE + kk + tig + 4]);
                a[fm][3] = __float_as_uint(As[(mr + 8) * A_STRIDE + kk + tig + 4]);
            }
#pragma unroll
            for (int fn = 0; fn < 4; fn++) {
                int nc = wn0 + fn * 8 + gid;
                b[fn][0] = __float_as_uint(Bs[(kk + tig) * B_STRIDE + nc]);
                b[fn][1] = __float_as_uint(Bs[(kk + tig + 4) * B_STRIDE + nc]);
            }
#pragma unroll
            for (int fm = 0; fm < 4; fm++)
#pragma unroll
                for (int fn = 0; fn < 4; fn++) mma_tf32(acc[fm][fn], a[fm], b[fn]);
        }
        __syncthreads();
        if (c + 2 < 8) LOAD_TILE(c + 2, buf);
    }
#undef LOAD_TILE

    // epilogue: bias + store
#pragma unroll
    for (int fm = 0; fm < 4; fm++) {
        int r0 = m0 + wm0 + fm * 16 + gid;
#pragma unroll
        for (int fn = 0; fn < 4; fn++) {
            int cidx = n0 + wn0 + fn * 8 + 2 * tig;
            float bv0 = __ldg(bias + cidx);
            float bv1 = __ldg(bias + cidx + 1);
            float2 v0 = make_float2(acc[fm][fn][0] + bv0, acc[fm][fn][1] + bv1);
            float2 v1 = make_float2(acc[fm][fn][2] + bv0, acc[fm][fn][3] + bv1);
            *(float2*)(out + (size_t)r0 * N + cidx) = v0;
            *(float2*)(out + (size_t)(r0 + 8) * N + cidx) = v1;
        }
    }
}

// ---------------------------------------------------------------------------
extern "C" void kernel_launch(void* const* d_in, const int* in_sizes, int n_in,
                              void* d_out, int out_size) {
    const float* x     = (const float*)d_in[0];
    const float* y     = (const float*)d_in[1];
    const float* W_tr  = (const float*)d_in[2];
    const float* b_tr  = (const float*)d_in[3];
    const float* W_pr  = (const float*)d_in[4];
    const float* b_pr  = (const float*)d_in[5];
    const float* W_cls = (const float*)d_in[6];
    const float* b_cls = (const float*)d_in[7];
    float* out = (float*)d_out;

    void *pXT, *pYP, *pZ, *pWr;
    cudaGetSymbolAddress(&pXT, g_XT);
    cudaGetSymbolAddress(&pYP, g_YP);
    cudaGetSymbolAddress(&pZ, g_Z);
    cudaGetSymbolAddress(&pWr, g_Wr);

    // W rounded to tf32 (so cp.async'd B operand is rna-rounded)
    round_w<<<(DJ * V_ / 4) / 256, 256>>>(W_cls, (float*)pWr);
    // XT = x @ W_tr + b_tr
    {
        dim3 grid((B_ * T_ + 63) / 64, DJ / 64);
        gemm_bias_f32<<<grid, 256>>>(x, W_tr, b_tr, (float*)pXT, B_ * T_, DTR);
    }
    // YP = y @ W_pr + b_pr
    {
        dim3 grid((B_ * U_ + 63) / 64, DJ / 64);
        gemm_bias_f32<<<grid, 256>>>(y, W_pr, b_pr, (float*)pYP, B_ * U_, DPR);
    }
    // Z = tf32(tanh(XT + YP))
    {
        int total4 = M_TOTAL * (DJ / 4);
        z_tanh_kernel<<<(total4 + 255) / 256, 256>>>((const float*)pXT,
                                                     (const float*)pYP, (float*)pZ);
    }
    // out = Z @ W_cls + b_cls
    {
        cudaFuncSetAttribute(joint_gemm_tf32, cudaFuncAttributeMaxDynamicSharedMemorySize,
                             SMEM_TOTAL_BYTES);
        dim3 grid(V_ / BN, M_TOTAL / BM);   // (8, 1250), N fastest for Z reuse
        joint_gemm_tf32<<<grid, 256, SMEM_TOTAL_BYTES>>>((const float*)pZ,
                                                         (const float*)pWr, b_cls, out);
    }
}